// round 10
// baseline (speedup 1.0000x reference)
#include <cuda_runtime.h>
#include <cuda_bf16.h>

// Problem constants (GatedMessageGcn_3126736191774)
#define RR   1000          // number of relations
#define DD   100           // feature dim
#define MM   2000000       // num_messages (segments)
#define EMAX 16000000      // edges

// ---------------------------------------------------------------------------
// Device scratch (static; no runtime allocation allowed)
// ---------------------------------------------------------------------------
__device__ float g_table[RR * RR];   // sigmoid(Gs @ Gr^T), 4 MB (L2-resident)
__device__ float g_denom[MM];        // segment sums, 8 MB   (L2-resident)
__device__ int   g_recv[EMAX];       // compacted receiver idx, 64 MB

// ---------------------------------------------------------------------------
// Kernel 1: 32x64-tile register-blocked GEMM (K=100) + sigmoid epilogue.
//   Grid = 32 x 16 = 512 blocks (3.5 CTAs/SM -> occupancy ~43%, vs 21% at
//   64x64/256 blocks). 256 threads; each computes a 2x4 sub-tile
//   (rows ty+16m, cols tx+16n; stride-101 smem -> conflict-free).
// ---------------------------------------------------------------------------
#define KPAD 101

__global__ void gemm_sigmoid_kernel(const float* __restrict__ Gs,
                                    const float* __restrict__ Gr) {
    __shared__ float As[32 * KPAD];   // sender rows   [row][k]
    __shared__ float Bs[64 * KPAD];   // receiver rows [row][k]

    const int tid = threadIdx.x;
    const int i0 = blockIdx.y * 32;
    const int j0 = blockIdx.x * 64;

    // Stage 32 sender rows (coalesced)
    for (int idx = tid; idx < 32 * DD; idx += 256) {
        int row = idx / DD;
        int k   = idx % DD;
        int gi = i0 + row;
        As[row * KPAD + k] = (gi < RR) ? Gs[gi * DD + k] : 0.0f;
    }
    // Stage 64 receiver rows (coalesced)
    for (int idx = tid; idx < 64 * DD; idx += 256) {
        int row = idx / DD;
        int k   = idx % DD;
        int gj = j0 + row;
        Bs[row * KPAD + k] = (gj < RR) ? Gr[gj * DD + k] : 0.0f;
    }
    __syncthreads();

    const int tx = tid & 15;   // col group: cols tx, tx+16, tx+32, tx+48
    const int ty = tid >> 4;   // row group: rows ty, ty+16

    float acc[2][4];
    #pragma unroll
    for (int m = 0; m < 2; m++)
        #pragma unroll
        for (int n = 0; n < 4; n++) acc[m][n] = 0.0f;

    #pragma unroll 4
    for (int k = 0; k < DD; k++) {
        float a0 = As[(ty     ) * KPAD + k];
        float a1 = As[(ty + 16) * KPAD + k];
        float b0 = Bs[(tx     ) * KPAD + k];
        float b1 = Bs[(tx + 16) * KPAD + k];
        float b2 = Bs[(tx + 32) * KPAD + k];
        float b3 = Bs[(tx + 48) * KPAD + k];

        acc[0][0] += a0 * b0; acc[0][1] += a0 * b1;
        acc[0][2] += a0 * b2; acc[0][3] += a0 * b3;
        acc[1][0] += a1 * b0; acc[1][1] += a1 * b1;
        acc[1][2] += a1 * b2; acc[1][3] += a1 * b3;
    }

    #pragma unroll
    for (int m = 0; m < 2; m++) {
        int i = i0 + ty + 16 * m;
        if (i >= RR) continue;
        #pragma unroll
        for (int n = 0; n < 4; n++) {
            int j = j0 + tx + 16 * n;
            if (j < RR)
                g_table[i * RR + j] = 1.0f / (1.0f + __expf(-acc[m][n]));
        }
    }
}

// ---------------------------------------------------------------------------
// Kernel 2 (pass 1): 4 edges/thread (champion config — DO NOT TOUCH).
//   4 independent table gathers, coalesced gate/recv stores, 4 REDG atomics.
// ---------------------------------------------------------------------------
__global__ void edge_pass1_kernel(const int4* __restrict__ rel4,
                                  const int4* __restrict__ msg4,
                                  float4* __restrict__ gates4,
                                  int E4) {
    int t = blockIdx.x * blockDim.x + threadIdx.x;
    if (t >= E4) return;

    int4 ra = rel4[2 * t];
    int4 rb = rel4[2 * t + 1];
    int4 ma = msg4[2 * t];
    int4 mb = msg4[2 * t + 1];

    float g0 = __ldg(&g_table[ra.x * RR + ra.y]);
    float g1 = __ldg(&g_table[ra.z * RR + ra.w]);
    float g2 = __ldg(&g_table[rb.x * RR + rb.y]);
    float g3 = __ldg(&g_table[rb.z * RR + rb.w]);

    gates4[t] = make_float4(g0, g1, g2, g3);
    reinterpret_cast<int4*>(g_recv)[t] = make_int4(ma.y, ma.w, mb.y, mb.w);

    atomicAdd(&g_denom[ma.y], g0);   // return unused -> REDG
    atomicAdd(&g_denom[ma.w], g1);
    atomicAdd(&g_denom[mb.y], g2);
    atomicAdd(&g_denom[mb.w], g3);
}

// ---------------------------------------------------------------------------
// Kernel 3 (pass 2): weights = gate / (denom[recv] + 1e-8), 4 edges/thread
// ---------------------------------------------------------------------------
__global__ void edge_pass2_kernel(float4* __restrict__ out4, int E4) {
    int t = blockIdx.x * blockDim.x + threadIdx.x;
    if (t >= E4) return;

    int4   r = reinterpret_cast<const int4*>(g_recv)[t];
    float4 g = out4[t];

    float d0 = __ldg(&g_denom[r.x]);
    float d1 = __ldg(&g_denom[r.y]);
    float d2 = __ldg(&g_denom[r.z]);
    float d3 = __ldg(&g_denom[r.w]);

    out4[t] = make_float4(g.x / (d0 + 1e-8f), g.y / (d1 + 1e-8f),
                          g.z / (d2 + 1e-8f), g.w / (d3 + 1e-8f));
}

// ---------------------------------------------------------------------------
// Scalar tails (E % 4 != 0 safety; E=16M so normally empty)
// ---------------------------------------------------------------------------
__global__ void edge_tail_kernel(const int2* __restrict__ rel,
                                 const int2* __restrict__ msg,
                                 float* __restrict__ gates,
                                 int start, int E) {
    int e = start + blockIdx.x * blockDim.x + threadIdx.x;
    if (e >= E) return;
    int2 rp = rel[e];
    int  rv = msg[e].y;
    float g = __ldg(&g_table[rp.x * RR + rp.y]);
    gates[e] = g;
    g_recv[e] = rv;
    atomicAdd(&g_denom[rv], g);
}

__global__ void edge_tail2_kernel(float* __restrict__ out,
                                  int start, int E) {
    int e = start + blockIdx.x * blockDim.x + threadIdx.x;
    if (e >= E) return;
    out[e] = out[e] / (__ldg(&g_denom[g_recv[e]]) + 1e-8f);
}

// ---------------------------------------------------------------------------
// Host helper: cached symbol address for memset (defined BEFORE use)
// ---------------------------------------------------------------------------
static void* denom_device_addr() {
    static void* p = nullptr;
    if (!p) cudaGetSymbolAddress(&p, g_denom);
    return p;
}

// ---------------------------------------------------------------------------
// Launch
// ---------------------------------------------------------------------------
extern "C" void kernel_launch(void* const* d_in, const int* in_sizes, int n_in,
                              void* d_out, int out_size) {
    const float* Gs = (const float*)d_in[0];
    const float* Gr = (const float*)d_in[1];
    const int4*  rel4 = (const int4*)d_in[2];
    const int4*  msg4 = (const int4*)d_in[3];
    float* out = (float*)d_out;

    int E  = in_sizes[2] / 2;   // (E,2) index pairs
    int E4 = E / 4;
    int tail = E - E4 * 4;

    // 1. zero denom (graph-capturable async memset)
    cudaMemsetAsync(denom_device_addr(), 0, (size_t)MM * sizeof(float));

    // 2. gate table (32x64 register-blocked GEMM + sigmoid)
    dim3 ggrid((RR + 63) / 64, (RR + 31) / 32);
    gemm_sigmoid_kernel<<<ggrid, 256>>>(Gs, Gr);

    // 3. pass 1: gates + segment sum
    int nblk = (E4 + 255) / 256;
    edge_pass1_kernel<<<nblk, 256>>>(rel4, msg4, (float4*)out, E4);
    if (tail) {
        edge_tail_kernel<<<1, 256>>>((const int2*)d_in[2], (const int2*)d_in[3],
                                     out, E4 * 4, E);
    }

    // 4. pass 2: normalize
    edge_pass2_kernel<<<nblk, 256>>>((float4*)out, E4);
    if (tail) {
        edge_tail2_kernel<<<1, 256>>>(out, E4 * 4, E);
    }
}

// round 11
// speedup vs baseline: 1.0351x; 1.0351x over previous
#include <cuda_runtime.h>
#include <cuda_bf16.h>

// Problem constants (GatedMessageGcn_3126736191774)
#define RR   1000          // number of relations
#define DD   100           // feature dim
#define MM   2000000       // num_messages (segments)
#define EMAX 16000000      // edges

// ---------------------------------------------------------------------------
// Device scratch (static; no runtime allocation allowed)
// ---------------------------------------------------------------------------
__device__ float g_table[RR * RR];   // sigmoid(Gs @ Gr^T), 4 MB (L2-resident)
__device__ float g_denom[MM];        // segment sums, 8 MB   (L2-resident)
__device__ int   g_recv[EMAX];       // compacted receiver idx, 64 MB

// ---------------------------------------------------------------------------
// Kernel 1: 64x64-tile GEMM (K=100) + sigmoid, transposed smem layout.
//   smem As/Bs are [k][row] with row-pad 68 (16B-aligned, conflict-free
//   vector reads). Each thread computes a contiguous 4x4 tile at
//   (4ty.., 4tx..): per k-step 2x LDS.128 + 16 FFMA; epilogue 4x STG.128.
// ---------------------------------------------------------------------------
#define RPAD 68   // row pad: 68*4B = 272B, 16B-aligned strides

__global__ void gemm_sigmoid_kernel(const float* __restrict__ Gs,
                                    const float* __restrict__ Gr) {
    __shared__ __align__(16) float As[DD * RPAD];   // [k][row] sender
    __shared__ __align__(16) float Bs[DD * RPAD];   // [k][row] receiver

    const int tid = threadIdx.x;
    const int i0 = blockIdx.y * 64;
    const int j0 = blockIdx.x * 64;

    // Stage: global [row][k] -> smem [k][row]
    for (int idx = tid; idx < 64 * DD; idx += 256) {
        int row = idx / DD;
        int k   = idx % DD;
        int gi = i0 + row;
        int gj = j0 + row;
        As[k * RPAD + row] = (gi < RR) ? Gs[gi * DD + k] : 0.0f;
        Bs[k * RPAD + row] = (gj < RR) ? Gr[gj * DD + k] : 0.0f;
    }
    __syncthreads();

    const int tx = tid & 15;   // cols 4tx .. 4tx+3 (contiguous)
    const int ty = tid >> 4;   // rows 4ty .. 4ty+3 (contiguous)

    float acc[4][4];
    #pragma unroll
    for (int m = 0; m < 4; m++)
        #pragma unroll
        for (int n = 0; n < 4; n++) acc[m][n] = 0.0f;

    #pragma unroll 2
    for (int k = 0; k < DD; k++) {
        float4 a = *reinterpret_cast<const float4*>(&As[k * RPAD + 4 * ty]);
        float4 b = *reinterpret_cast<const float4*>(&Bs[k * RPAD + 4 * tx]);

        acc[0][0] += a.x * b.x; acc[0][1] += a.x * b.y; acc[0][2] += a.x * b.z; acc[0][3] += a.x * b.w;
        acc[1][0] += a.y * b.x; acc[1][1] += a.y * b.y; acc[1][2] += a.y * b.z; acc[1][3] += a.y * b.w;
        acc[2][0] += a.z * b.x; acc[2][1] += a.z * b.y; acc[2][2] += a.z * b.z; acc[2][3] += a.z * b.w;
        acc[3][0] += a.w * b.x; acc[3][1] += a.w * b.y; acc[3][2] += a.w * b.z; acc[3][3] += a.w * b.w;
    }

    const int jb = j0 + 4 * tx;
    #pragma unroll
    for (int m = 0; m < 4; m++) {
        int i = i0 + 4 * ty + m;
        if (i >= RR) continue;
        float4 v;
        v.x = 1.0f / (1.0f + __expf(-acc[m][0]));
        v.y = 1.0f / (1.0f + __expf(-acc[m][1]));
        v.z = 1.0f / (1.0f + __expf(-acc[m][2]));
        v.w = 1.0f / (1.0f + __expf(-acc[m][3]));
        if (jb + 3 < RR) {
            // RR = 1000 and jb are multiples of 4 -> 16B aligned
            *reinterpret_cast<float4*>(&g_table[i * RR + jb]) = v;
        } else {
            float vv[4] = {v.x, v.y, v.z, v.w};
            #pragma unroll
            for (int n = 0; n < 4; n++)
                if (jb + n < RR) g_table[i * RR + jb + n] = vv[n];
        }
    }
}

// ---------------------------------------------------------------------------
// Kernel 2 (pass 1): 4 edges/thread (champion config — frozen).
//   4 independent table gathers, coalesced gate/recv stores, 4 REDG atomics.
// ---------------------------------------------------------------------------
__global__ void edge_pass1_kernel(const int4* __restrict__ rel4,
                                  const int4* __restrict__ msg4,
                                  float4* __restrict__ gates4,
                                  int E4) {
    int t = blockIdx.x * blockDim.x + threadIdx.x;
    if (t >= E4) return;

    int4 ra = rel4[2 * t];
    int4 rb = rel4[2 * t + 1];
    int4 ma = msg4[2 * t];
    int4 mb = msg4[2 * t + 1];

    float g0 = __ldg(&g_table[ra.x * RR + ra.y]);
    float g1 = __ldg(&g_table[ra.z * RR + ra.w]);
    float g2 = __ldg(&g_table[rb.x * RR + rb.y]);
    float g3 = __ldg(&g_table[rb.z * RR + rb.w]);

    gates4[t] = make_float4(g0, g1, g2, g3);
    reinterpret_cast<int4*>(g_recv)[t] = make_int4(ma.y, ma.w, mb.y, mb.w);

    atomicAdd(&g_denom[ma.y], g0);   // return unused -> REDG
    atomicAdd(&g_denom[ma.w], g1);
    atomicAdd(&g_denom[mb.y], g2);
    atomicAdd(&g_denom[mb.w], g3);
}

// ---------------------------------------------------------------------------
// Kernel 3 (pass 2): weights = gate / (denom[recv] + 1e-8), 4 edges/thread
// ---------------------------------------------------------------------------
__global__ void edge_pass2_kernel(float4* __restrict__ out4, int E4) {
    int t = blockIdx.x * blockDim.x + threadIdx.x;
    if (t >= E4) return;

    int4   r = reinterpret_cast<const int4*>(g_recv)[t];
    float4 g = out4[t];

    float d0 = __ldg(&g_denom[r.x]);
    float d1 = __ldg(&g_denom[r.y]);
    float d2 = __ldg(&g_denom[r.z]);
    float d3 = __ldg(&g_denom[r.w]);

    out4[t] = make_float4(g.x / (d0 + 1e-8f), g.y / (d1 + 1e-8f),
                          g.z / (d2 + 1e-8f), g.w / (d3 + 1e-8f));
}

// ---------------------------------------------------------------------------
// Scalar tails (E % 4 != 0 safety; E=16M so normally empty)
// ---------------------------------------------------------------------------
__global__ void edge_tail_kernel(const int2* __restrict__ rel,
                                 const int2* __restrict__ msg,
                                 float* __restrict__ gates,
                                 int start, int E) {
    int e = start + blockIdx.x * blockDim.x + threadIdx.x;
    if (e >= E) return;
    int2 rp = rel[e];
    int  rv = msg[e].y;
    float g = __ldg(&g_table[rp.x * RR + rp.y]);
    gates[e] = g;
    g_recv[e] = rv;
    atomicAdd(&g_denom[rv], g);
}

__global__ void edge_tail2_kernel(float* __restrict__ out,
                                  int start, int E) {
    int e = start + blockIdx.x * blockDim.x + threadIdx.x;
    if (e >= E) return;
    out[e] = out[e] / (__ldg(&g_denom[g_recv[e]]) + 1e-8f);
}

// ---------------------------------------------------------------------------
// Host helper: cached symbol address for memset (defined BEFORE use)
// ---------------------------------------------------------------------------
static void* denom_device_addr() {
    static void* p = nullptr;
    if (!p) cudaGetSymbolAddress(&p, g_denom);
    return p;
}

// ---------------------------------------------------------------------------
// Launch
// ---------------------------------------------------------------------------
extern "C" void kernel_launch(void* const* d_in, const int* in_sizes, int n_in,
                              void* d_out, int out_size) {
    const float* Gs = (const float*)d_in[0];
    const float* Gr = (const float*)d_in[1];
    const int4*  rel4 = (const int4*)d_in[2];
    const int4*  msg4 = (const int4*)d_in[3];
    float* out = (float*)d_out;

    int E  = in_sizes[2] / 2;   // (E,2) index pairs
    int E4 = E / 4;
    int tail = E - E4 * 4;

    // 1. zero denom (graph-capturable async memset)
    cudaMemsetAsync(denom_device_addr(), 0, (size_t)MM * sizeof(float));

    // 2. gate table (64x64 GEMM, transposed smem, vector LDS/STG)
    dim3 ggrid((RR + 63) / 64, (RR + 63) / 64);
    gemm_sigmoid_kernel<<<ggrid, 256>>>(Gs, Gr);

    // 3. pass 1: gates + segment sum
    int nblk = (E4 + 255) / 256;
    edge_pass1_kernel<<<nblk, 256>>>(rel4, msg4, (float4*)out, E4);
    if (tail) {
        edge_tail_kernel<<<1, 256>>>((const int2*)d_in[2], (const int2*)d_in[3],
                                     out, E4 * 4, E);
    }

    // 4. pass 2: normalize
    edge_pass2_kernel<<<nblk, 256>>>((float4*)out, E4);
    if (tail) {
        edge_tail2_kernel<<<1, 256>>>(out, E4 * 4, E);
    }
}